// round 1
// baseline (speedup 1.0000x reference)
#include <cuda_runtime.h>

#define BB 32
#define NN 2048
#define CIN 64
#define COUTC 128
#define ADJ_EPS 1e-6f
#define BN_EPS 1e-5f

// Scratch (device globals — no allocations allowed)
__device__ float g_invS[BB * NN];                 // 1/(rowsum+eps)
__device__ float g_h[(size_t)BB * NN * COUTC];    // pre-BN activations, [b][m][o]
__device__ float g_stats[2 * COUTC];              // per-channel sum, sumsq

// ---------------------------------------------------------------------------
// K1: row sums of A over last axis; also zeroes g_stats (block 0).
// One warp per row (2048 contiguous floats).
// ---------------------------------------------------------------------------
__global__ void k_rowsum(const float* __restrict__ A) {
    if (blockIdx.x == 0 && threadIdx.x < 2 * COUTC) g_stats[threadIdx.x] = 0.f;
    int row = blockIdx.x * (blockDim.x >> 5) + (threadIdx.x >> 5);
    int lane = threadIdx.x & 31;
    if (row >= BB * NN) return;
    const float4* Ar = reinterpret_cast<const float4*>(A + (size_t)row * NN);
    float s = 0.f;
#pragma unroll 4
    for (int i = lane; i < NN / 4; i += 32) {
        float4 v = Ar[i];
        s += v.x + v.y + v.z + v.w;
    }
#pragma unroll
    for (int o = 16; o; o >>= 1) s += __shfl_xor_sync(0xFFFFFFFFu, s, o);
    if (lane == 0) g_invS[row] = 1.0f / (s + ADJ_EPS);
}

// ---------------------------------------------------------------------------
// K2: per (batch, m-tile of 128):
//   xg[m, c] = sum_n A[b][n][m] * (x[b][n][c] * invS[b][n])      (K = 2048)
//   h[m, o]  = sum_c xg[m, c] * W[o][c] + bias[o]
//   accumulate BN stats (sum, sumsq per o), write h to g_h[b][m][o]
// 256 threads; main loop: each thread owns 8(m) x 4(c) accumulators.
// ---------------------------------------------------------------------------
__global__ void __launch_bounds__(256) k_gemm(const float* __restrict__ A,
                                              const float* __restrict__ x,
                                              const float* __restrict__ W,
                                              const float* __restrict__ bias) {
    __shared__ float smem[8192];          // 32KB: loop = invS(2048)+Atile(2048)+xtile(1024); epi = xg(8192)
    __shared__ float s_sum[COUTC], s_sq[COUTC];

    float* s_invS = smem;                 // [2048]
    float* s_A    = smem + 2048;          // [16][128]
    float* s_x    = smem + 4096;          // [16][64]

    const int tid = threadIdx.x;
    const int bb  = blockIdx.y;
    const int m0  = blockIdx.x * 128;
    const int tx  = tid & 15;             // c-group (4 c's) in loop, o-group (8 o's) in epi
    const int ty  = tid >> 4;             // m-group (8 m's)

    const float* Ab = A + (size_t)bb * NN * NN;
    const float* xb = x + (size_t)bb * NN * CIN;

    for (int i = tid; i < NN; i += 256) s_invS[i] = g_invS[bb * NN + i];
    __syncthreads();

    float acc[8][4];
#pragma unroll
    for (int i = 0; i < 8; i++)
#pragma unroll
        for (int j = 0; j < 4; j++) acc[i][j] = 0.f;

    for (int k0 = 0; k0 < NN; k0 += 16) {
        // A tile: 16 rows x 128 cols = 512 float4, 2 per thread
#pragma unroll
        for (int l = 0; l < 2; l++) {
            int idx = tid + l * 256;
            int r = idx >> 5, c4 = idx & 31;
            float4 v = *reinterpret_cast<const float4*>(Ab + (size_t)(k0 + r) * NN + m0 + c4 * 4);
            *reinterpret_cast<float4*>(&s_A[r * 128 + c4 * 4]) = v;
        }
        // x tile: 16 rows x 64 cols = 256 float4, 1 per thread, scaled by invS
        {
            int r = tid >> 4, c4 = tid & 15;
            float sc = s_invS[k0 + r];
            float4 v = *reinterpret_cast<const float4*>(xb + (size_t)(k0 + r) * CIN + c4 * 4);
            v.x *= sc; v.y *= sc; v.z *= sc; v.w *= sc;
            *reinterpret_cast<float4*>(&s_x[r * 64 + c4 * 4]) = v;
        }
        __syncthreads();
#pragma unroll
        for (int kk = 0; kk < 16; kk++) {
            float4 a0 = *reinterpret_cast<const float4*>(&s_A[kk * 128 + ty * 8]);
            float4 a1 = *reinterpret_cast<const float4*>(&s_A[kk * 128 + ty * 8 + 4]);
            float4 xv = *reinterpret_cast<const float4*>(&s_x[kk * 64 + tx * 4]);
            float am[8] = {a0.x, a0.y, a0.z, a0.w, a1.x, a1.y, a1.z, a1.w};
            float xm[4] = {xv.x, xv.y, xv.z, xv.w};
#pragma unroll
            for (int i = 0; i < 8; i++)
#pragma unroll
                for (int j = 0; j < 4; j++)
                    acc[i][j] = fmaf(am[i], xm[j], acc[i][j]);
        }
        __syncthreads();
    }

    // ---- epilogue: xg -> smem, then h = xg @ W^T + bias, stats, store ----
#pragma unroll
    for (int i = 0; i < 8; i++)
#pragma unroll
        for (int j = 0; j < 4; j++)
            smem[(ty * 8 + i) * 64 + tx * 4 + j] = acc[i][j];
    if (tid < COUTC) { s_sum[tid] = 0.f; s_sq[tid] = 0.f; }
    __syncthreads();

    const float4* W4 = reinterpret_cast<const float4*>(W);  // W[o][c], 16 float4 per row
    // each thread: m rows ty*8..+7, o columns tx*8..+7, processed 2 o's at a time
#pragma unroll
    for (int op = 0; op < 4; op++) {
        int o0 = tx * 8 + op * 2;
        float h0[8], h1[8];
#pragma unroll
        for (int mi = 0; mi < 8; mi++) { h0[mi] = 0.f; h1[mi] = 0.f; }
#pragma unroll
        for (int c4 = 0; c4 < 16; c4++) {
            float4 w0 = W4[(size_t)o0 * 16 + c4];
            float4 w1 = W4[(size_t)(o0 + 1) * 16 + c4];
#pragma unroll
            for (int mi = 0; mi < 8; mi++) {
                float4 g = *reinterpret_cast<const float4*>(&smem[(ty * 8 + mi) * 64 + c4 * 4]);
                h0[mi] += g.x * w0.x + g.y * w0.y + g.z * w0.z + g.w * w0.w;
                h1[mi] += g.x * w1.x + g.y * w1.y + g.z * w1.z + g.w * w1.w;
            }
        }
        float b0 = bias[o0], b1 = bias[o0 + 1];
        float s0 = 0.f, q0 = 0.f, s1 = 0.f, q1 = 0.f;
        size_t base = ((size_t)bb * NN + m0 + ty * 8) * COUTC + o0;
#pragma unroll
        for (int mi = 0; mi < 8; mi++) {
            float v0 = h0[mi] + b0;
            float v1 = h1[mi] + b1;
            s0 += v0; q0 += v0 * v0;
            s1 += v1; q1 += v1 * v1;
            *reinterpret_cast<float2*>(&g_h[base + (size_t)mi * COUTC]) = make_float2(v0, v1);
        }
        atomicAdd(&s_sum[o0], s0);     atomicAdd(&s_sq[o0], q0);
        atomicAdd(&s_sum[o0 + 1], s1); atomicAdd(&s_sq[o0 + 1], q1);
    }
    __syncthreads();
    if (tid < COUTC)           atomicAdd(&g_stats[tid], s_sum[tid]);
    else if (tid < 2 * COUTC)  atomicAdd(&g_stats[tid], s_sq[tid - COUTC]);
}

// ---------------------------------------------------------------------------
// K3: BN finalize + ReLU. g_h layout == output layout -> pure elementwise.
// ---------------------------------------------------------------------------
__global__ void k_bn(float* __restrict__ out,
                     const float* __restrict__ gamma,
                     const float* __restrict__ beta) {
    __shared__ float s_scale[COUTC], s_shift[COUTC];
    if (threadIdx.x < COUTC) {
        int o = threadIdx.x;
        float cnt = (float)(BB * NN);
        float mean = g_stats[o] / cnt;
        float var  = g_stats[o + COUTC] / cnt - mean * mean;
        float sc   = gamma[o] * rsqrtf(var + BN_EPS);
        s_scale[o] = sc;
        s_shift[o] = beta[o] - mean * sc;
    }
    __syncthreads();
    const size_t total = (size_t)BB * NN * COUTC / 4;
    const float4* h4 = reinterpret_cast<const float4*>(g_h);
    float4* o4 = reinterpret_cast<float4*>(out);
    for (size_t idx = (size_t)blockIdx.x * blockDim.x + threadIdx.x; idx < total;
         idx += (size_t)gridDim.x * blockDim.x) {
        float4 v = h4[idx];
        int o = ((int)idx & 31) * 4;   // 32 float4 per 128-wide row
        v.x = fmaxf(fmaf(v.x, s_scale[o + 0], s_shift[o + 0]), 0.f);
        v.y = fmaxf(fmaf(v.y, s_scale[o + 1], s_shift[o + 1]), 0.f);
        v.z = fmaxf(fmaf(v.z, s_scale[o + 2], s_shift[o + 2]), 0.f);
        v.w = fmaxf(fmaf(v.w, s_scale[o + 3], s_shift[o + 3]), 0.f);
        o4[idx] = v;
    }
}

extern "C" void kernel_launch(void* const* d_in, const int* in_sizes, int n_in,
                              void* d_out, int out_size) {
    const float* x     = (const float*)d_in[0];
    const float* A     = (const float*)d_in[1];
    const float* W     = (const float*)d_in[2];
    const float* bias  = (const float*)d_in[3];
    const float* gamma = (const float*)d_in[4];
    const float* beta  = (const float*)d_in[5];
    float* out = (float*)d_out;

    k_rowsum<<<BB * NN / 8, 256>>>(A);
    dim3 g2(NN / 128, BB);
    k_gemm<<<g2, 256>>>(A, x, W, bias);
    k_bn<<<4096, 256>>>(out, gamma, beta);
}

// round 4
// speedup vs baseline: 1.8249x; 1.8249x over previous
#include <cuda_runtime.h>
#include <cstdint>

#define BB 32
#define NN 2048
#define CIN 64
#define COUTC 128
#define ADJ_EPS 1e-6f
#define BN_EPS 1e-5f

// smem geometry (floats)
#define SA_STRIDE 36          // 36 % 32 == 4 -> conflict-free a-frag LDS
#define SB_STRIDE 136         // 136 % 32 == 8 -> conflict-free b-frag LDS
#define SA_BYTES (64 * SA_STRIDE * 4)    // 9216
#define SB_BYTES (32 * SB_STRIDE * 4)    // 17408
#define STAGE_BYTES (SA_BYTES + SB_BYTES)  // 26624
#define SMEM_BYTES (2 * STAGE_BYTES)       // 53248

// ---------------- scratch (device globals; no allocations allowed) ----------
__device__ float g_invS[BB * NN];
__device__ float g_xsT[(size_t)BB * 64 * NN];      // xsT[b][c][n] = tf32(x[b][n][c]*invS)
__device__ float g_h[(size_t)BB * NN * COUTC];     // pre-BN activations [b][m][o]
__device__ float g_stats[2 * COUTC];

__device__ __forceinline__ uint32_t smem_u32(const void* p) {
    uint32_t a;
    asm("{ .reg .u64 t; cvta.to.shared.u64 t, %1; cvt.u32.u64 %0, t; }" : "=r"(a) : "l"(p));
    return a;
}
__device__ __forceinline__ void cp16(uint32_t dst, const void* src) {
    asm volatile("cp.async.cg.shared.global [%0], [%1], 16;" :: "r"(dst), "l"(src));
}

// ---------------------------------------------------------------------------
// K1: row sums of A (one warp per row); block 0 zeroes g_stats.
// ---------------------------------------------------------------------------
__global__ void k_rowsum(const float* __restrict__ A) {
    if (blockIdx.x == 0 && threadIdx.x < 2 * COUTC) g_stats[threadIdx.x] = 0.f;
    int row = blockIdx.x * (blockDim.x >> 5) + (threadIdx.x >> 5);
    int lane = threadIdx.x & 31;
    if (row >= BB * NN) return;
    const float4* Ar = reinterpret_cast<const float4*>(A + (size_t)row * NN);
    float s = 0.f;
#pragma unroll 4
    for (int i = lane; i < NN / 4; i += 32) {
        float4 v = Ar[i];
        s += v.x + v.y + v.z + v.w;
    }
#pragma unroll
    for (int o = 16; o; o >>= 1) s += __shfl_xor_sync(0xFFFFFFFFu, s, o);
    if (lane == 0) g_invS[row] = 1.0f / (s + ADJ_EPS);
}

// ---------------------------------------------------------------------------
// K1b: xsT[b][c][n] = tf32(x[b][n][c] * invS[b][n]), transposed via smem
// ---------------------------------------------------------------------------
__global__ void __launch_bounds__(256) k_prep(const float* __restrict__ x) {
    __shared__ float sx[64 * 65];
    __shared__ float sinv[64];
    const int b = blockIdx.y, n0 = blockIdx.x * 64, tid = threadIdx.x;
    if (tid < 64) sinv[tid] = g_invS[b * NN + n0 + tid];
#pragma unroll
    for (int l = 0; l < 4; l++) {
        int i = tid + 256 * l;
        int n = i >> 4, c4 = i & 15;
        float4 v = *reinterpret_cast<const float4*>(x + ((size_t)b * NN + n0 + n) * 64 + c4 * 4);
        sx[n * 65 + c4 * 4 + 0] = v.x;
        sx[n * 65 + c4 * 4 + 1] = v.y;
        sx[n * 65 + c4 * 4 + 2] = v.z;
        sx[n * 65 + c4 * 4 + 3] = v.w;
    }
    __syncthreads();
#pragma unroll
    for (int l = 0; l < 16; l++) {
        int i = tid + 256 * l;
        int c = i >> 6, n = i & 63;
        float v = sx[n * 65 + c] * sinv[n];
        uint32_t u;
        asm("cvt.rna.tf32.f32 %0, %1;" : "=r"(u) : "f"(v));
        g_xsT[((size_t)b * 64 + c) * NN + n0 + n] = __uint_as_float(u);
    }
}

// ---------------------------------------------------------------------------
// K2: warp-level tf32 mma.sync GEMM + fused 1x1 conv + BN stats.
// Per CTA: D[c(64), m(128)] = sum_n xsT[c][n] * A[n][m0+m], K = 2048.
//   mma m16n8k8 .row.col: A-op = xsT (row-major), B-op = adjacency (col-major
//   [K][N] == stored [n][m] row-major: exactly A's native layout, no transpose)
// ---------------------------------------------------------------------------
__global__ void __launch_bounds__(256, 2) k_gemm(const float* __restrict__ A,
                                                 const float* __restrict__ Wm,
                                                 const float* __restrict__ bias) {
    extern __shared__ float sm[];
    __shared__ float s_sum[COUTC], s_sq[COUTC];

    const uint32_t smb = smem_u32(sm);
    const int tid = threadIdx.x;
    const int w = tid >> 5, lane = tid & 31;
    const int bb = blockIdx.y, m0 = blockIdx.x * 128;
    const float* Ab = A + (size_t)bb * NN * NN;
    const float* xT = g_xsT + (size_t)bb * 64 * NN;

    float acc[4][2][4];
#pragma unroll
    for (int mt = 0; mt < 4; mt++)
#pragma unroll
        for (int nt = 0; nt < 2; nt++)
#pragma unroll
            for (int j = 0; j < 4; j++) acc[mt][nt][j] = 0.f;

    // ---- prefetch chunk 0 ----
    {
        uint32_t sa = smb, sb = smb + SA_BYTES;
#pragma unroll
        for (int l = 0; l < 2; l++) {
            int i = tid + 256 * l, c = i >> 3, q = i & 7;
            cp16(sa + c * (SA_STRIDE * 4) + q * 16, xT + (size_t)c * NN + q * 4);
        }
#pragma unroll
        for (int l = 0; l < 4; l++) {
            int i = tid + 256 * l, n = i >> 5, q = i & 31;
            cp16(sb + n * (SB_STRIDE * 4) + q * 16, Ab + (size_t)n * NN + m0 + q * 4);
        }
        asm volatile("cp.async.commit_group;");
    }

    for (int ch = 0; ch < 64; ch++) {
        const int s = ch & 1;
        if (ch + 1 < 64) {
            const int k0 = (ch + 1) * 32;
            uint32_t sa = smb + (s ^ 1) * STAGE_BYTES, sb = sa + SA_BYTES;
#pragma unroll
            for (int l = 0; l < 2; l++) {
                int i = tid + 256 * l, c = i >> 3, q = i & 7;
                cp16(sa + c * (SA_STRIDE * 4) + q * 16, xT + (size_t)c * NN + k0 + q * 4);
            }
#pragma unroll
            for (int l = 0; l < 4; l++) {
                int i = tid + 256 * l, n = i >> 5, q = i & 31;
                cp16(sb + n * (SB_STRIDE * 4) + q * 16, Ab + (size_t)(k0 + n) * NN + m0 + q * 4);
            }
        }
        asm volatile("cp.async.commit_group;");
        asm volatile("cp.async.wait_group 1;");
        __syncthreads();

        const float* sA = sm + s * (STAGE_BYTES / 4);
        const float* sB = sA + SA_BYTES / 4;
        const int ar = lane >> 2, ac = lane & 3;

#pragma unroll
        for (int ks = 0; ks < 4; ks++) {
            const int kc = ks * 8;
            uint32_t a[4][4];
#pragma unroll
            for (int mt = 0; mt < 4; mt++) {
                const float* base = sA + (mt * 16 + ar) * SA_STRIDE + kc + ac;
                a[mt][0] = __float_as_uint(base[0]);
                a[mt][1] = __float_as_uint(base[8 * SA_STRIDE]);
                a[mt][2] = __float_as_uint(base[4]);
                a[mt][3] = __float_as_uint(base[8 * SA_STRIDE + 4]);
            }
            uint32_t b[2][2];
#pragma unroll
            for (int nt = 0; nt < 2; nt++) {
                const float* base = sB + (kc + ac) * SB_STRIDE + w * 16 + nt * 8 + ar;
                b[nt][0] = __float_as_uint(base[0]);
                b[nt][1] = __float_as_uint(base[4 * SB_STRIDE]);
            }
#pragma unroll
            for (int mt = 0; mt < 4; mt++)
#pragma unroll
                for (int nt = 0; nt < 2; nt++)
                    asm volatile(
                        "mma.sync.aligned.m16n8k8.row.col.f32.tf32.tf32.f32 "
                        "{%0,%1,%2,%3}, {%4,%5,%6,%7}, {%8,%9}, {%0,%1,%2,%3};"
                        : "+f"(acc[mt][nt][0]), "+f"(acc[mt][nt][1]),
                          "+f"(acc[mt][nt][2]), "+f"(acc[mt][nt][3])
                        : "r"(a[mt][0]), "r"(a[mt][1]), "r"(a[mt][2]), "r"(a[mt][3]),
                          "r"(b[nt][0]), "r"(b[nt][1]));
        }
        __syncthreads();
    }

    // ---- accumulators -> smem xg[m][68 stride] (conflict-free scatter) ----
#pragma unroll
    for (int mt = 0; mt < 4; mt++)
#pragma unroll
        for (int nt = 0; nt < 2; nt++) {
            int cr = mt * 16 + (lane >> 2);
            int mc = w * 16 + nt * 8 + 2 * (lane & 3);
            sm[mc * 68 + cr]           = acc[mt][nt][0];
            sm[(mc + 1) * 68 + cr]     = acc[mt][nt][1];
            sm[mc * 68 + cr + 8]       = acc[mt][nt][2];
            sm[(mc + 1) * 68 + cr + 8] = acc[mt][nt][3];
        }
    if (tid < COUTC) { s_sum[tid] = 0.f; s_sq[tid] = 0.f; }
    __syncthreads();

    // ---- epilogue: h = xg @ W^T + bias, BN stats, store h ----
    const float4* W4 = reinterpret_cast<const float4*>(Wm);
    const int tx = tid & 15, ty = tid >> 4;
#pragma unroll
    for (int op = 0; op < 4; op++) {
        int o0 = tx * 8 + op * 2;
        float h0[8], h1[8];
#pragma unroll
        for (int mi = 0; mi < 8; mi++) { h0[mi] = 0.f; h1[mi] = 0.f; }
#pragma unroll
        for (int c4 = 0; c4 < 16; c4++) {
            float4 w0 = W4[(size_t)o0 * 16 + c4];
            float4 w1 = W4[(size_t)(o0 + 1) * 16 + c4];
#pragma unroll
            for (int mi = 0; mi < 8; mi++) {
                float4 g = *reinterpret_cast<const float4*>(&sm[(ty * 8 + mi) * 68 + c4 * 4]);
                h0[mi] += g.x * w0.x + g.y * w0.y + g.z * w0.z + g.w * w0.w;
                h1[mi] += g.x * w1.x + g.y * w1.y + g.z * w1.z + g.w * w1.w;
            }
        }
        float b0 = bias[o0], b1 = bias[o0 + 1];
        float sA2 = 0.f, qA = 0.f, sB2 = 0.f, qB = 0.f;
        size_t base = ((size_t)bb * NN + m0 + ty * 8) * COUTC + o0;
#pragma unroll
        for (int mi = 0; mi < 8; mi++) {
            float v0 = h0[mi] + b0, v1 = h1[mi] + b1;
            sA2 += v0; qA += v0 * v0;
            sB2 += v1; qB += v1 * v1;
            *reinterpret_cast<float2*>(&g_h[base + (size_t)mi * COUTC]) = make_float2(v0, v1);
        }
        atomicAdd(&s_sum[o0], sA2);     atomicAdd(&s_sq[o0], qA);
        atomicAdd(&s_sum[o0 + 1], sB2); atomicAdd(&s_sq[o0 + 1], qB);
    }
    __syncthreads();
    if (tid < COUTC)          atomicAdd(&g_stats[tid], s_sum[tid]);
    else if (tid < 2 * COUTC) atomicAdd(&g_stats[tid], s_sq[tid - COUTC]);
}

// ---------------------------------------------------------------------------
// K3: BN finalize + ReLU (g_h layout == output layout)
// ---------------------------------------------------------------------------
__global__ void k_bn(float* __restrict__ out,
                     const float* __restrict__ gamma,
                     const float* __restrict__ beta) {
    __shared__ float s_scale[COUTC], s_shift[COUTC];
    if (threadIdx.x < COUTC) {
        int o = threadIdx.x;
        float cnt = (float)(BB * NN);
        float mean = g_stats[o] / cnt;
        float var = g_stats[o + COUTC] / cnt - mean * mean;
        float sc = gamma[o] * rsqrtf(var + BN_EPS);
        s_scale[o] = sc;
        s_shift[o] = beta[o] - mean * sc;
    }
    __syncthreads();
    const size_t total = (size_t)BB * NN * COUTC / 4;
    const float4* h4 = reinterpret_cast<const float4*>(g_h);
    float4* o4 = reinterpret_cast<float4*>(out);
    for (size_t idx = (size_t)blockIdx.x * blockDim.x + threadIdx.x; idx < total;
         idx += (size_t)gridDim.x * blockDim.x) {
        float4 v = h4[idx];
        int o = ((int)idx & 31) * 4;
        v.x = fmaxf(fmaf(v.x, s_scale[o + 0], s_shift[o + 0]), 0.f);
        v.y = fmaxf(fmaf(v.y, s_scale[o + 1], s_shift[o + 1]), 0.f);
        v.z = fmaxf(fmaf(v.z, s_scale[o + 2], s_shift[o + 2]), 0.f);
        v.w = fmaxf(fmaf(v.w, s_scale[o + 3], s_shift[o + 3]), 0.f);
        o4[idx] = v;
    }
}

extern "C" void kernel_launch(void* const* d_in, const int* in_sizes, int n_in,
                              void* d_out, int out_size) {
    const float* x     = (const float*)d_in[0];
    const float* A     = (const float*)d_in[1];
    const float* W     = (const float*)d_in[2];
    const float* bias  = (const float*)d_in[3];
    const float* gamma = (const float*)d_in[4];
    const float* beta  = (const float*)d_in[5];
    float* out = (float*)d_out;

    cudaFuncSetAttribute(k_gemm, cudaFuncAttributeMaxDynamicSharedMemorySize, SMEM_BYTES);

    k_rowsum<<<BB * NN / 8, 256>>>(A);
    dim3 gp(NN / 64, BB);
    k_prep<<<gp, 256>>>(x);
    dim3 g2(NN / 128, BB);
    k_gemm<<<g2, 256, SMEM_BYTES>>>(A, W, bias);
    k_bn<<<4096, 256>>>(out, gamma, beta);
}

// round 5
// speedup vs baseline: 1.8718x; 1.0257x over previous
#include <cuda_runtime.h>
#include <cstdint>

#define BB 32
#define NN 2048
#define CIN 64
#define COUTC 128
#define ADJ_EPS 1e-6f
#define BN_EPS 1e-5f

// smem geometry (floats)
#define SA_STRIDE 36          // 36 % 32 == 4 -> conflict-free a-frag LDS
#define SB_STRIDE 136         // 136 % 32 == 8 -> conflict-free b-frag LDS
#define SA_BYTES (64 * SA_STRIDE * 4)    // 9216
#define SB_BYTES (32 * SB_STRIDE * 4)    // 17408
#define STAGE_BYTES (SA_BYTES + SB_BYTES)  // 26624
#define NSTAGE 3
#define SMEM_BYTES (NSTAGE * STAGE_BYTES)  // 79872

// ---------------- scratch (device globals; no allocations allowed) ----------
__device__ float g_invS[BB * NN];
__device__ float g_xsT[(size_t)BB * 64 * NN];      // xsT[b][c][n] = tf32(x[b][n][c]*invS)
__device__ float g_h[(size_t)BB * NN * COUTC];     // pre-BN activations [b][m][o]
__device__ float g_stats[2 * COUTC];

__device__ __forceinline__ uint32_t smem_u32(const void* p) {
    uint32_t a;
    asm("{ .reg .u64 t; cvta.to.shared.u64 t, %1; cvt.u32.u64 %0, t; }" : "=r"(a) : "l"(p));
    return a;
}
__device__ __forceinline__ void cp16(uint32_t dst, const void* src) {
    asm volatile("cp.async.cg.shared.global [%0], [%1], 16;" :: "r"(dst), "l"(src));
}

// ---------------------------------------------------------------------------
// K1: row sums of A (one warp per row); block 0 zeroes g_stats.
// ---------------------------------------------------------------------------
__global__ void k_rowsum(const float* __restrict__ A) {
    if (blockIdx.x == 0 && threadIdx.x < 2 * COUTC) g_stats[threadIdx.x] = 0.f;
    int row = blockIdx.x * (blockDim.x >> 5) + (threadIdx.x >> 5);
    int lane = threadIdx.x & 31;
    if (row >= BB * NN) return;
    const float4* Ar = reinterpret_cast<const float4*>(A + (size_t)row * NN);
    float s = 0.f;
#pragma unroll 4
    for (int i = lane; i < NN / 4; i += 32) {
        float4 v = Ar[i];
        s += v.x + v.y + v.z + v.w;
    }
#pragma unroll
    for (int o = 16; o; o >>= 1) s += __shfl_xor_sync(0xFFFFFFFFu, s, o);
    if (lane == 0) g_invS[row] = 1.0f / (s + ADJ_EPS);
}

// ---------------------------------------------------------------------------
// K1b: xsT[b][c][n] = tf32(x[b][n][c] * invS[b][n]), transposed via smem
// ---------------------------------------------------------------------------
__global__ void __launch_bounds__(256) k_prep(const float* __restrict__ x) {
    __shared__ float sx[64 * 65];
    __shared__ float sinv[64];
    const int b = blockIdx.y, n0 = blockIdx.x * 64, tid = threadIdx.x;
    if (tid < 64) sinv[tid] = g_invS[b * NN + n0 + tid];
#pragma unroll
    for (int l = 0; l < 4; l++) {
        int i = tid + 256 * l;
        int n = i >> 4, c4 = i & 15;
        float4 v = *reinterpret_cast<const float4*>(x + ((size_t)b * NN + n0 + n) * 64 + c4 * 4);
        sx[n * 65 + c4 * 4 + 0] = v.x;
        sx[n * 65 + c4 * 4 + 1] = v.y;
        sx[n * 65 + c4 * 4 + 2] = v.z;
        sx[n * 65 + c4 * 4 + 3] = v.w;
    }
    __syncthreads();
#pragma unroll
    for (int l = 0; l < 16; l++) {
        int i = tid + 256 * l;
        int c = i >> 6, n = i & 63;
        float v = sx[n * 65 + c] * sinv[n];
        uint32_t u;
        asm("cvt.rna.tf32.f32 %0, %1;" : "=r"(u) : "f"(v));
        g_xsT[((size_t)b * 64 + c) * NN + n0 + n] = __uint_as_float(u);
    }
}

// ---------------------------------------------------------------------------
// K2: warp-level tf32 mma.sync GEMM + fused 1x1 conv + BN stats.
// Per CTA: D[c(64), m(128)] = sum_n xsT[c][n] * A[n][m0+m], K = 2048.
// 3-stage cp.async ring, one __syncthreads per chunk.
// ---------------------------------------------------------------------------
__global__ void __launch_bounds__(256, 2) k_gemm(const float* __restrict__ A,
                                                 const float* __restrict__ Wm,
                                                 const float* __restrict__ bias) {
    extern __shared__ float sm[];
    __shared__ float s_sum[COUTC], s_sq[COUTC];

    const uint32_t smb = smem_u32(sm);
    const int tid = threadIdx.x;
    const int w = tid >> 5, lane = tid & 31;
    const int bb = blockIdx.y, m0 = blockIdx.x * 128;
    const float* Ab = A + (size_t)bb * NN * NN;
    const float* xT = g_xsT + (size_t)bb * 64 * NN;

    float acc[4][2][4];
#pragma unroll
    for (int mt = 0; mt < 4; mt++)
#pragma unroll
        for (int nt = 0; nt < 2; nt++)
#pragma unroll
            for (int j = 0; j < 4; j++) acc[mt][nt][j] = 0.f;

    // per-thread load offsets (constant across chunks)
    const int la_c = tid >> 3, la_q = tid & 7;          // +256: c+=32
    const int lb_n = tid >> 5, lb_q = tid & 31;         // +256: n+=8

    // ---- prologue: issue chunks 0 and 1 into stages 0 and 1 ----
#pragma unroll
    for (int p = 0; p < 2; p++) {
        const int k0 = p * 32;
        uint32_t sa = smb + p * STAGE_BYTES, sb = sa + SA_BYTES;
        cp16(sa + la_c * (SA_STRIDE * 4) + la_q * 16, xT + (size_t)la_c * NN + k0 + la_q * 4);
        cp16(sa + (la_c + 32) * (SA_STRIDE * 4) + la_q * 16, xT + (size_t)(la_c + 32) * NN + k0 + la_q * 4);
#pragma unroll
        for (int l = 0; l < 4; l++)
            cp16(sb + (lb_n + 8 * l) * (SB_STRIDE * 4) + lb_q * 16,
                 Ab + (size_t)(k0 + lb_n + 8 * l) * NN + m0 + lb_q * 4);
        asm volatile("cp.async.commit_group;");
    }

    const int ar = lane >> 2, ac = lane & 3;

    for (int ch = 0; ch < 64; ch++) {
        const int s = ch % NSTAGE;
        asm volatile("cp.async.wait_group 1;");
        __syncthreads();

        const float* sA = sm + s * (STAGE_BYTES / 4);
        const float* sB = sA + SA_BYTES / 4;

#pragma unroll
        for (int ks = 0; ks < 4; ks++) {
            const int kc = ks * 8;
            uint32_t a[4][4];
#pragma unroll
            for (int mt = 0; mt < 4; mt++) {
                const float* base = sA + (mt * 16 + ar) * SA_STRIDE + kc + ac;
                a[mt][0] = __float_as_uint(base[0]);
                a[mt][1] = __float_as_uint(base[8 * SA_STRIDE]);
                a[mt][2] = __float_as_uint(base[4]);
                a[mt][3] = __float_as_uint(base[8 * SA_STRIDE + 4]);
            }
            uint32_t b[2][2];
#pragma unroll
            for (int nt = 0; nt < 2; nt++) {
                const float* base = sB + (kc + ac) * SB_STRIDE + w * 16 + nt * 8 + ar;
                b[nt][0] = __float_as_uint(base[0]);
                b[nt][1] = __float_as_uint(base[4 * SB_STRIDE]);
            }
#pragma unroll
            for (int mt = 0; mt < 4; mt++)
#pragma unroll
                for (int nt = 0; nt < 2; nt++)
                    asm volatile(
                        "mma.sync.aligned.m16n8k8.row.col.f32.tf32.tf32.f32 "
                        "{%0,%1,%2,%3}, {%4,%5,%6,%7}, {%8,%9}, {%0,%1,%2,%3};"
                        : "+f"(acc[mt][nt][0]), "+f"(acc[mt][nt][1]),
                          "+f"(acc[mt][nt][2]), "+f"(acc[mt][nt][3])
                        : "r"(a[mt][0]), "r"(a[mt][1]), "r"(a[mt][2]), "r"(a[mt][3]),
                          "r"(b[nt][0]), "r"(b[nt][1]));
        }

        // issue loads for chunk ch+2 into stage (ch+2)%3 (computed in iter ch-1,
        // all warps past it thanks to this iteration's leading __syncthreads)
        if (ch + 2 < 64) {
            const int k0 = (ch + 2) * 32;
            uint32_t sa = smb + ((ch + 2) % NSTAGE) * STAGE_BYTES, sb = sa + SA_BYTES;
            cp16(sa + la_c * (SA_STRIDE * 4) + la_q * 16, xT + (size_t)la_c * NN + k0 + la_q * 4);
            cp16(sa + (la_c + 32) * (SA_STRIDE * 4) + la_q * 16, xT + (size_t)(la_c + 32) * NN + k0 + la_q * 4);
#pragma unroll
            for (int l = 0; l < 4; l++)
                cp16(sb + (lb_n + 8 * l) * (SB_STRIDE * 4) + lb_q * 16,
                     Ab + (size_t)(k0 + lb_n + 8 * l) * NN + m0 + lb_q * 4);
        }
        asm volatile("cp.async.commit_group;");
    }
    __syncthreads();   // all compute done before smem is reused for xg

    // ---- accumulators -> smem xg[m][68 stride] (conflict-free scatter) ----
#pragma unroll
    for (int mt = 0; mt < 4; mt++)
#pragma unroll
        for (int nt = 0; nt < 2; nt++) {
            int cr = mt * 16 + (lane >> 2);
            int mc = w * 16 + nt * 8 + 2 * (lane & 3);
            sm[mc * 68 + cr]           = acc[mt][nt][0];
            sm[(mc + 1) * 68 + cr]     = acc[mt][nt][1];
            sm[mc * 68 + cr + 8]       = acc[mt][nt][2];
            sm[(mc + 1) * 68 + cr + 8] = acc[mt][nt][3];
        }
    if (tid < COUTC) { s_sum[tid] = 0.f; s_sq[tid] = 0.f; }
    __syncthreads();

    // ---- epilogue: h = xg @ W^T + bias, BN stats, store h ----
    const float4* W4 = reinterpret_cast<const float4*>(Wm);
    const int tx = tid & 15, ty = tid >> 4;
#pragma unroll
    for (int op = 0; op < 4; op++) {
        int o0 = tx * 8 + op * 2;
        float h0[8], h1[8];
#pragma unroll
        for (int mi = 0; mi < 8; mi++) { h0[mi] = 0.f; h1[mi] = 0.f; }
#pragma unroll
        for (int c4 = 0; c4 < 16; c4++) {
            float4 w0 = W4[(size_t)o0 * 16 + c4];
            float4 w1 = W4[(size_t)(o0 + 1) * 16 + c4];
#pragma unroll
            for (int mi = 0; mi < 8; mi++) {
                float4 g = *reinterpret_cast<const float4*>(&sm[(ty * 8 + mi) * 68 + c4 * 4]);
                h0[mi] += g.x * w0.x + g.y * w0.y + g.z * w0.z + g.w * w0.w;
                h1[mi] += g.x * w1.x + g.y * w1.y + g.z * w1.z + g.w * w1.w;
            }
        }
        float b0 = bias[o0], b1 = bias[o0 + 1];
        float sA2 = 0.f, qA = 0.f, sB2 = 0.f, qB = 0.f;
        size_t base = ((size_t)bb * NN + m0 + ty * 8) * COUTC + o0;
#pragma unroll
        for (int mi = 0; mi < 8; mi++) {
            float v0 = h0[mi] + b0, v1 = h1[mi] + b1;
            sA2 += v0; qA += v0 * v0;
            sB2 += v1; qB += v1 * v1;
            *reinterpret_cast<float2*>(&g_h[base + (size_t)mi * COUTC]) = make_float2(v0, v1);
        }
        atomicAdd(&s_sum[o0], sA2);     atomicAdd(&s_sq[o0], qA);
        atomicAdd(&s_sum[o0 + 1], sB2); atomicAdd(&s_sq[o0 + 1], qB);
    }
    __syncthreads();
    if (tid < COUTC)          atomicAdd(&g_stats[tid], s_sum[tid]);
    else if (tid < 2 * COUTC) atomicAdd(&g_stats[tid], s_sq[tid - COUTC]);
}

// ---------------------------------------------------------------------------
// K3: BN finalize + ReLU (g_h layout == output layout)
// ---------------------------------------------------------------------------
__global__ void k_bn(float* __restrict__ out,
                     const float* __restrict__ gamma,
                     const float* __restrict__ beta) {
    __shared__ float s_scale[COUTC], s_shift[COUTC];
    if (threadIdx.x < COUTC) {
        int o = threadIdx.x;
        float cnt = (float)(BB * NN);
        float mean = g_stats[o] / cnt;
        float var = g_stats[o + COUTC] / cnt - mean * mean;
        float sc = gamma[o] * rsqrtf(var + BN_EPS);
        s_scale[o] = sc;
        s_shift[o] = beta[o] - mean * sc;
    }
    __syncthreads();
    const size_t total = (size_t)BB * NN * COUTC / 4;
    const float4* h4 = reinterpret_cast<const float4*>(g_h);
    float4* o4 = reinterpret_cast<float4*>(out);
    for (size_t idx = (size_t)blockIdx.x * blockDim.x + threadIdx.x; idx < total;
         idx += (size_t)gridDim.x * blockDim.x) {
        float4 v = h4[idx];
        int o = ((int)idx & 31) * 4;
        v.x = fmaxf(fmaf(v.x, s_scale[o + 0], s_shift[o + 0]), 0.f);
        v.y = fmaxf(fmaf(v.y, s_scale[o + 1], s_shift[o + 1]), 0.f);
        v.z = fmaxf(fmaf(v.z, s_scale[o + 2], s_shift[o + 2]), 0.f);
        v.w = fmaxf(fmaf(v.w, s_scale[o + 3], s_shift[o + 3]), 0.f);
        o4[idx] = v;
    }
}

extern "C" void kernel_launch(void* const* d_in, const int* in_sizes, int n_in,
                              void* d_out, int out_size) {
    const float* x     = (const float*)d_in[0];
    const float* A     = (const float*)d_in[1];
    const float* W     = (const float*)d_in[2];
    const float* bias  = (const float*)d_in[3];
    const float* gamma = (const float*)d_in[4];
    const float* beta  = (const float*)d_in[5];
    float* out = (float*)d_out;

    cudaFuncSetAttribute(k_gemm, cudaFuncAttributeMaxDynamicSharedMemorySize, SMEM_BYTES);

    k_rowsum<<<BB * NN / 8, 256>>>(A);
    dim3 gp(NN / 64, BB);
    k_prep<<<gp, 256>>>(x);
    dim3 g2(NN / 128, BB);
    k_gemm<<<g2, 256, SMEM_BYTES>>>(A, W, bias);
    k_bn<<<4096, 256>>>(out, gamma, beta);
}